// round 9
// baseline (speedup 1.0000x reference)
#include <cuda_runtime.h>
#include <cstdint>

#define BGRAPHS   16
#define NPG       2048
#define KNN       16
#define MIN_DISTR 5
#define CPB       32                 // centers per block
#define PARTS     8                  // threads per center
#define CANDS     (NPG / PARTS)      // 256 candidates per part
#define THREADS   (CPB * PARTS)      // 256 threads per block
#define CAP       128                // pass-2 collection capacity per center

// monotone float -> uint key (total order matching float <)
__device__ __forceinline__ unsigned sortkey(float f)
{
    unsigned u = __float_as_uint(f);
    return u ^ (unsigned)(((int)u >> 31) | 0x80000000);
}

// exact reference-rounded squared distance (validated rounds 3-8)
__device__ __forceinline__ float d2_ref(float cx, float cy, float cz, float csq,
                                        const float4 v)
{
    float dot = __fmaf_rn(cz, v.z, __fmaf_rn(cy, v.y, __fmul_rn(cx, v.x)));
    return __fmaf_rn(-2.0f, dot, __fadd_rn(csq, v.w));
}

__global__ __launch_bounds__(THREADS, 5)
void knn_kernel(const float* __restrict__ pos, float2* __restrict__ out)
{
    __shared__ float4         sh[NPG];            // 32 KB: x,y,z,|p|^2
    __shared__ float          h1s[CPB * PARTS];   //  1 KB: per-part 2nd-smallest
    __shared__ float          bnd[CPB];
    __shared__ int            cnt[CPB];
    __shared__ unsigned short jbuf[CPB * CAP];    //  8 KB

    const int tid = threadIdx.x;
    const int p   = tid >> 5;        // part 0..7 (uniform per warp)
    const int c   = tid & 31;        // center-in-block (lane)

    const int g  = blockIdx.x >> 6;           // 64 blocks per graph
    const int cb = (blockIdx.x & 63) * CPB;   // center base (local)
    const int gb = g * NPG;

    if (tid < CPB) cnt[tid] = 0;

    // ---- load whole graph; sq per reference rounding ----
    for (int i = tid; i < NPG; i += THREADS) {
        const float* q = pos + 3ull * (unsigned long long)(gb + i);
        float x = q[0], y = q[1], z = q[2];
        float sq = __fadd_rn(__fadd_rn(__fmul_rn(x, x), __fmul_rn(y, y)),
                             __fmul_rn(z, z));
        sh[i] = make_float4(x, y, z, sq);
    }
    __syncthreads();

    const int    lc = cb + c;
    const float4 cc = sh[lc];
    const float  cx = cc.x, cy = cc.y, cz = cc.z, csq = cc.w;
    const float  INF = __int_as_float(0x7f800000);

    // ---- pass 1: exact 2-smallest of this part's non-self candidates ----
    // two interleaved 2-smallest chains (even/odd j) double the spacing of
    // the loop-carried FMNMX dependency; merged exactly afterwards.
    float a0 = INF, a1 = INF;        // even-j chain (sorted: a0 <= a1)
    float b0 = INF, b1 = INF;        // odd-j chain
    const int jb = p * CANDS;
#pragma unroll 8
    for (int j = jb; j < jb + CANDS; j += 2) {
        float de = d2_ref(cx, cy, cz, csq, sh[j]);
        float dq = d2_ref(cx, cy, cz, csq, sh[j + 1]);
        de = (j == lc)     ? INF : de;      // exclude self
        dq = (j + 1 == lc) ? INF : dq;
        float t0 = fminf(a0, de), xa = fmaxf(a0, de);
        a0 = t0; a1 = fminf(a1, xa);
        float t1 = fminf(b0, dq), xb = fmaxf(b0, dq);
        b0 = t1; b1 = fminf(b1, xb);
    }
    // exact 2nd-smallest of the union of both chains
    h1s[c * PARTS + p] = fminf(fmaxf(a0, b0), fminf(a1, b1));
    __syncthreads();

    // ---- bound: max of the 8 per-part 2nd-smallest values ----
    // each part contributes 2 distinct non-self elements <= its h1 <= B
    // => >=16 non-self elements <= B => B >= true 16th smallest
    if (tid < CPB) {
        const float* H = h1s + tid * PARTS;
        float B = H[0];
#pragma unroll
        for (int e = 1; e < PARTS; ++e) B = fmaxf(B, H[e]);
        bnd[tid] = B;
    }
    __syncthreads();

    // ---- pass 2: collect candidate indices with d2 <= B (self included) ----
    const float B = bnd[c];
#pragma unroll 4
    for (int j = jb; j < jb + CANDS; ++j) {
        float dd = d2_ref(cx, cy, cz, csq, sh[j]);
        if (dd <= B) {
            int s = atomicAdd(&cnt[c], 1);
            if (s < CAP) jbuf[c * CAP + s] = (unsigned short)j;
        }
    }
    __syncthreads();

    // ---- selection + filters + emit: one lane per center ----
    if (tid < CPB) {
        const int    lc2 = cb + tid;
        const float4 c0  = sh[lc2];
        const float  ax = c0.x, ay = c0.y, az = c0.z, asq = c0.w;

        unsigned long long hd[KNN];
#pragma unroll
        for (int t = 0; t < KNN; ++t) hd[t] = ~0ull;

        const int m = cnt[tid];
        if (m <= CAP) {
            for (int e = 0; e < m; ++e) {
                const int j = jbuf[tid * CAP + e];
                if (j == lc2) continue;          // skip self
                float d2 = d2_ref(ax, ay, az, asq, sh[j]);
                unsigned long long key =
                    ((unsigned long long)sortkey(d2) << 32) | (unsigned)j;
                if (key < hd[KNN - 1]) {
#pragma unroll
                    for (int t = 0; t < KNN; ++t) {
                        unsigned long long lo = key < hd[t] ? key : hd[t];
                        unsigned long long hi = key < hd[t] ? hd[t] : key;
                        hd[t] = lo; key = hi;
                    }
                }
            }
        } else {
            // overflow fallback: exact full scan (deterministic, ~never)
            for (int j = 0; j < NPG; ++j) {
                if (j == lc2) continue;
                float d2 = d2_ref(ax, ay, az, asq, sh[j]);
                unsigned long long key =
                    ((unsigned long long)sortkey(d2) << 32) | (unsigned)j;
                if (key < hd[KNN - 1]) {
#pragma unroll
                    for (int t = 0; t < KNN; ++t) {
                        unsigned long long lo = key < hd[t] ? key : hd[t];
                        unsigned long long hi = key < hd[t] ? hd[t] : key;
                        hd[t] = lo; key = hi;
                    }
                }
            }
        }

        const int ctr = gb + lc2;
#pragma unroll
        for (int k = 0; k < KNN; ++k) {
            float2 e = make_float2(-1.0f, -1.0f);
            if (hd[k] != ~0ull) {
                const int nl  = (int)(unsigned)(hd[k] & 0xFFFFFFFFull);
                const int nbr = gb + nl;
                const float4 v = sh[nl];
                // degenerate-edge filter, reference formula
                float dx = __fadd_rn(v.x, -ax);
                float dy = __fadd_rn(v.y, -ay);
                float dz = __fadd_rn(v.z, -az);
                float dn2 = __fadd_rn(__fadd_rn(__fmul_rn(dx, dx),
                                                __fmul_rn(dy, dy)),
                                      __fmul_rn(dz, dz));
                int  rd    = nbr > ctr ? (nbr - ctr) : (ctr - nbr);
                bool valid = (rd >= MIN_DISTR) && (sqrtf(dn2) >= 1e-10f);
                if (valid) e = make_float2((float)nbr, (float)ctr);
            }
            out[ctr * KNN + k] = e;
        }
    }
}

extern "C" void kernel_launch(void* const* d_in, const int* in_sizes, int n_in,
                              void* d_out, int out_size)
{
    const float* pos = (const float*)d_in[0];
    for (int i = 0; i < n_in; ++i)
        if (in_sizes[i] == BGRAPHS * NPG * 3) { pos = (const float*)d_in[i]; break; }
    float2* out = (float2*)d_out;

    dim3 grid(BGRAPHS * (NPG / CPB));   // 1024 blocks
    dim3 block(THREADS);                // 256 threads
    knn_kernel<<<grid, block>>>(pos, out);
}

// round 10
// speedup vs baseline: 1.2038x; 1.2038x over previous
#include <cuda_runtime.h>
#include <cstdint>

#define BGRAPHS   16
#define NPG       2048
#define KNN       16
#define MIN_DISTR 5
#define CPB       32                 // centers per block
#define PARTS     8                  // threads per center
#define CANDS     (NPG / PARTS)      // 256 candidates per part
#define THREADS   (CPB * PARTS)      // 256 threads per block
#define CAPG      128                // per-center collection capacity (global scratch)

// global scratch for pass-2 collected indices (static device array: no allocation)
__device__ unsigned short g_jbuf[(size_t)BGRAPHS * NPG * CAPG];   // 8 MB

// monotone float -> uint key (total order matching float <)
__device__ __forceinline__ unsigned sortkey(float f)
{
    unsigned u = __float_as_uint(f);
    return u ^ (unsigned)(((int)u >> 31) | 0x80000000);
}

// exact reference-rounded squared distance (validated rounds 3-9)
__device__ __forceinline__ float d2_ref(float cx, float cy, float cz, float csq,
                                        const float4 v)
{
    float dot = __fmaf_rn(cz, v.z, __fmaf_rn(cy, v.y, __fmul_rn(cx, v.x)));
    return __fmaf_rn(-2.0f, dot, __fadd_rn(csq, v.w));
}

__global__ __launch_bounds__(THREADS, 6)
void knn_kernel(const float* __restrict__ pos, float2* __restrict__ out)
{
    __shared__ float4 sh[NPG];                 // 32 KB: x,y,z,|p|^2
    __shared__ float  pvals[CPB * PARTS * 3];  //  3 KB: per-part 3 smallest
    __shared__ float  bnd[CPB];
    __shared__ int    cnt[CPB];

    const int tid = threadIdx.x;
    const int p   = tid >> 5;        // part 0..7 (uniform per warp)
    const int c   = tid & 31;        // center-in-block (lane)

    const int g  = blockIdx.x >> 6;           // 64 blocks per graph
    const int cb = (blockIdx.x & 63) * CPB;   // center base (local)
    const int gb = g * NPG;

    if (tid < CPB) cnt[tid] = 0;

    // ---- load graph into smem: {x,y,z,|p|^2} (sq per reference rounding) ----
    for (int i = tid; i < NPG; i += THREADS) {
        const float* q = pos + 3ull * (unsigned long long)(gb + i);
        float x = q[0], y = q[1], z = q[2];
        float sq = __fadd_rn(__fadd_rn(__fmul_rn(x, x), __fmul_rn(y, y)),
                             __fmul_rn(z, z));
        sh[i] = make_float4(x, y, z, sq);
    }
    __syncthreads();

    const int    lc = cb + c;
    const float4 cc = sh[lc];
    const float  cx = cc.x, cy = cc.y, cz = cc.z, csq = cc.w;
    const float  INF = __int_as_float(0x7f800000);

    // ---- pass 1: 3 smallest of this part's substream (R5-proven, branchless) ----
    float h0 = INF, h1 = INF, h2 = INF;
    const int jb = p * CANDS;
#pragma unroll 8
    for (int j = jb; j < jb + CANDS; ++j) {
        const float4 v = sh[j];
        float d2 = d2_ref(cx, cy, cz, csq, v);
        d2 = (j == lc) ? INF : d2;             // exclude self
        float t0 = fminf(h0, d2), x1 = fmaxf(h0, d2); h0 = t0;
        float t1 = fminf(h1, x1), x2 = fmaxf(h1, x1); h1 = t1;
        h2 = fminf(h2, x2);
    }
    {
        float* pv = pvals + (c * PARTS + p) * 3;
        pv[0] = h0; pv[1] = h1; pv[2] = h2;
    }
    __syncthreads();

    // ---- bound: 16th smallest of the 24 part-values (= 9th largest) ----
    if (tid < CPB) {
        float g9[9];
#pragma unroll
        for (int t = 0; t < 9; ++t) g9[t] = -INF;
        const float* pv = pvals + tid * PARTS * 3;
        for (int e = 0; e < PARTS * 3; ++e) {
            float x = pv[e];
#pragma unroll
            for (int t = 0; t < 9; ++t) {
                float hi = fmaxf(g9[t], x);
                x = fminf(g9[t], x);
                g9[t] = hi;
            }
        }
        bnd[tid] = g9[8];   // >= true 16th-smallest d2 (union's 16 smallest
                            // are 16 distinct non-self elements <= it)
    }
    __syncthreads();

    // ---- pass 2: collect candidate indices with d2 <= bound (self included) ----
    const float B = bnd[c];
    unsigned short* jrow = g_jbuf + (size_t)(gb + lc) * CAPG;
#pragma unroll 4
    for (int j = jb; j < jb + CANDS; ++j) {
        float dd = d2_ref(cx, cy, cz, csq, sh[j]);
        if (dd <= B) {
            int s = atomicAdd(&cnt[c], 1);
            if (s < CAPG) jrow[s] = (unsigned short)j;
        }
    }
    __syncthreads();

    // ---- selection + filters + emit: one lane per center ----
    if (tid < CPB) {
        const int    lc2 = cb + tid;
        const float4 c0  = sh[lc2];
        const float  ax = c0.x, ay = c0.y, az = c0.z, asq = c0.w;

        unsigned long long hd[KNN];
#pragma unroll
        for (int t = 0; t < KNN; ++t) hd[t] = ~0ull;

        const int m = cnt[tid];
        const unsigned short* row = g_jbuf + (size_t)(gb + lc2) * CAPG;
        if (m <= CAPG) {
            for (int e = 0; e < m; ++e) {
                const int j = row[e];
                if (j == lc2) continue;          // skip self
                float d2 = d2_ref(ax, ay, az, asq, sh[j]);
                unsigned long long key =
                    ((unsigned long long)sortkey(d2) << 32) | (unsigned)j;
                if (key < hd[KNN - 1]) {
#pragma unroll
                    for (int t = 0; t < KNN; ++t) {
                        unsigned long long lo = key < hd[t] ? key : hd[t];
                        unsigned long long hi = key < hd[t] ? hd[t] : key;
                        hd[t] = lo; key = hi;
                    }
                }
            }
        } else {
            // overflow fallback: exact full scan (deterministic, ~never)
            for (int j = 0; j < NPG; ++j) {
                if (j == lc2) continue;
                float d2 = d2_ref(ax, ay, az, asq, sh[j]);
                unsigned long long key =
                    ((unsigned long long)sortkey(d2) << 32) | (unsigned)j;
                if (key < hd[KNN - 1]) {
#pragma unroll
                    for (int t = 0; t < KNN; ++t) {
                        unsigned long long lo = key < hd[t] ? key : hd[t];
                        unsigned long long hi = key < hd[t] ? hd[t] : key;
                        hd[t] = lo; key = hi;
                    }
                }
            }
        }

        const int ctr = gb + lc2;
#pragma unroll
        for (int k = 0; k < KNN; ++k) {
            float2 e = make_float2(-1.0f, -1.0f);
            if (hd[k] != ~0ull) {
                const int nl  = (int)(unsigned)(hd[k] & 0xFFFFFFFFull);
                const int nbr = gb + nl;
                const float4 v = sh[nl];
                // degenerate-edge filter, reference formula
                float dx = __fadd_rn(v.x, -ax);
                float dy = __fadd_rn(v.y, -ay);
                float dz = __fadd_rn(v.z, -az);
                float dn2 = __fadd_rn(__fadd_rn(__fmul_rn(dx, dx),
                                                __fmul_rn(dy, dy)),
                                      __fmul_rn(dz, dz));
                int  rd    = nbr > ctr ? (nbr - ctr) : (ctr - nbr);
                bool valid = (rd >= MIN_DISTR) && (sqrtf(dn2) >= 1e-10f);
                if (valid) e = make_float2((float)nbr, (float)ctr);
            }
            out[ctr * KNN + k] = e;
        }
    }
}

extern "C" void kernel_launch(void* const* d_in, const int* in_sizes, int n_in,
                              void* d_out, int out_size)
{
    const float* pos = (const float*)d_in[0];
    for (int i = 0; i < n_in; ++i)
        if (in_sizes[i] == BGRAPHS * NPG * 3) { pos = (const float*)d_in[i]; break; }
    float2* out = (float2*)d_out;

    dim3 grid(BGRAPHS * (NPG / CPB));   // 1024 blocks
    dim3 block(THREADS);                // 256 threads
    knn_kernel<<<grid, block>>>(pos, out);
}